// round 2
// baseline (speedup 1.0000x reference)
#include <cuda_runtime.h>
#include <cstdint>

#define VV 4096
#define HH 128
#define MVV 20
#define NMAX 50000
#define ETYPES_MAX 512
#define BMAX 64

// ---------------- static scratch (no runtime allocation allowed) ----------------
__device__ __align__(16) float g_xA[(size_t)NMAX * HH];
__device__ __align__(16) float g_xB[(size_t)NMAX * HH];
__device__ __align__(16) float g_node_lin[VV * HH];
__device__ __align__(16) float g_edge_lin[ETYPES_MAX * HH];
__device__ __align__(16) float g_relmsg[ETYPES_MAX * HH];
__device__ __align__(16) float g_attn[BMAX * VV];
__device__ float g_beta[BMAX * MVV];
__device__ __align__(16) float g_pooled[BMAX * HH];
__device__ float g_cnt[BMAX];

// ---------------- fused alpha GEMM + softmax(axis=MV) + beta reduce ----------------
// attn[b,v] = sum_mv softmax_mv( vn[b,:,: ] @ aw[v,:] ) * beta[b,mv]
// block: (v-tile of 256, one b). 128 threads: cg=tid>>2 owns cols {cg+32j}, mg=tid&3 owns mv {mg*5+i}
__global__ __launch_bounds__(128) void attn_kernel(
    const float* __restrict__ vn,    // [B][MV][V]
    const float* __restrict__ aw,    // [V][V] layer slice
    const float* __restrict__ beta,  // [B][MV]
    float* __restrict__ attn)        // [B][V]
{
    __shared__ float sA[MVV][33];
    __shared__ float sB[256][33];
    __shared__ float sBeta[MVV];
    const int b = blockIdx.y;
    const int vbase = blockIdx.x * 256;
    const int tid = threadIdx.x;
    const int cg = tid >> 2;
    const int mg = tid & 3;
    if (tid < MVV) sBeta[tid] = beta[b * MVV + tid];
    const float* vnb = vn + (size_t)b * MVV * VV;

    float acc[5][8];
#pragma unroll
    for (int i = 0; i < 5; i++)
#pragma unroll
        for (int j = 0; j < 8; j++) acc[i][j] = 0.f;

    for (int k0 = 0; k0 < VV; k0 += 32) {
        // A tile: 20x32
#pragma unroll
        for (int idx = tid; idx < MVV * 32; idx += 128) {
            sA[idx >> 5][idx & 31] = vnb[(size_t)(idx >> 5) * VV + k0 + (idx & 31)];
        }
        // B tile: 256 rows x 32 (K-major rows of alpha_w)
#pragma unroll
        for (int f = tid; f < 2048; f += 128) {
            int row = f >> 3, c4 = f & 7;
            float4 v = *reinterpret_cast<const float4*>(aw + (size_t)(vbase + row) * VV + k0 + c4 * 4);
            float* p = &sB[row][c4 * 4];
            p[0] = v.x; p[1] = v.y; p[2] = v.z; p[3] = v.w;
        }
        __syncthreads();
#pragma unroll 4
        for (int k = 0; k < 32; k++) {
            float a[5], bb[8];
#pragma unroll
            for (int i = 0; i < 5; i++) a[i] = sA[mg * 5 + i][k];
#pragma unroll
            for (int j = 0; j < 8; j++) bb[j] = sB[cg + 32 * j][k];
#pragma unroll
            for (int i = 0; i < 5; i++)
#pragma unroll
                for (int j = 0; j < 8; j++) acc[i][j] = fmaf(a[i], bb[j], acc[i][j]);
        }
        __syncthreads();
    }

    // softmax over mv (20 values spread across 4 threads mg=0..3, same warp), weighted by beta.
    // alpha_b is constant along the softmax axis -> cancels exactly -> omitted.
#pragma unroll
    for (int j = 0; j < 8; j++) {
        float mx = -1e30f;
#pragma unroll
        for (int i = 0; i < 5; i++) mx = fmaxf(mx, acc[i][j]);
        mx = fmaxf(mx, __shfl_xor_sync(0xffffffffu, mx, 1));
        mx = fmaxf(mx, __shfl_xor_sync(0xffffffffu, mx, 2));
        float se = 0.f, sw = 0.f;
#pragma unroll
        for (int i = 0; i < 5; i++) {
            float e = __expf(acc[i][j] - mx);
            se += e;
            sw += e * sBeta[mg * 5 + i];
        }
        se += __shfl_xor_sync(0xffffffffu, se, 1);
        sw += __shfl_xor_sync(0xffffffffu, sw, 1);
        se += __shfl_xor_sync(0xffffffffu, se, 2);
        sw += __shfl_xor_sync(0xffffffffu, sw, 2);
        if (mg == 0) attn[(size_t)b * VV + vbase + cg + 32 * j] = sw / se;
    }
}

// ---------------- beta[b,mv] = tanh(vn[b,mv,:] . bw + bb) * exp(0.01*(MV-mv)) ----------------
__global__ void beta_kernel(const float* __restrict__ vn, const float* __restrict__ bw,
                            const float* __restrict__ bb, float* __restrict__ beta, int BMV)
{
    int gw = (blockIdx.x * blockDim.x + threadIdx.x) >> 5;
    int lane = threadIdx.x & 31;
    if (gw >= BMV) return;
    int mv = gw % MVV;
    const float* row = vn + (size_t)gw * VV;
    float s = 0.f;
    for (int k = lane; k < VV; k += 32) s = fmaf(row[k], bw[k], s);
#pragma unroll
    for (int o = 16; o > 0; o >>= 1) s += __shfl_xor_sync(0xffffffffu, s, o);
    if (lane == 0) beta[gw] = tanhf(s + bb[0]) * __expf(0.01f * (float)(MVV - mv));
}

// ---------------- generic out[r,c] = act( (a1[r,:] + s*a2[r,:]) @ w[c,:] + bias[c] ), K=N=128 ----------------
__global__ __launch_bounds__(256) void gemm128_kernel(
    const float* __restrict__ a1, const float* __restrict__ a2,
    const float* __restrict__ epsp, int layer,
    const float* __restrict__ w, const float* __restrict__ bias,
    float* __restrict__ out, int M, int relu)
{
    __shared__ float sIn[128][33];
    __shared__ float sW[128][33];
    const int tid = threadIdx.x;
    const int rg = tid >> 4, cg = tid & 15;
    const int rbase = blockIdx.x * 128;
    float scale = 0.f;
    if (a2) scale = 1.0f + epsp[layer];

    float acc[8][8];
#pragma unroll
    for (int i = 0; i < 8; i++)
#pragma unroll
        for (int j = 0; j < 8; j++) acc[i][j] = 0.f;

    for (int k0 = 0; k0 < 128; k0 += 32) {
#pragma unroll
        for (int f = tid; f < 1024; f += 256) {
            int row = f >> 3, c4 = f & 7;
            int r = rbase + row;
            float4 v = make_float4(0.f, 0.f, 0.f, 0.f);
            if (r < M) {
                v = *reinterpret_cast<const float4*>(a1 + (size_t)r * 128 + k0 + c4 * 4);
                if (a2) {
                    float4 u = *reinterpret_cast<const float4*>(a2 + (size_t)r * 128 + k0 + c4 * 4);
                    v.x = fmaf(scale, u.x, v.x); v.y = fmaf(scale, u.y, v.y);
                    v.z = fmaf(scale, u.z, v.z); v.w = fmaf(scale, u.w, v.w);
                }
            }
            float* p = &sIn[row][c4 * 4];
            p[0] = v.x; p[1] = v.y; p[2] = v.z; p[3] = v.w;
        }
#pragma unroll
        for (int f = tid; f < 1024; f += 256) {
            int row = f >> 3, c4 = f & 7;
            float4 v = *reinterpret_cast<const float4*>(w + (size_t)row * 128 + k0 + c4 * 4);
            float* p = &sW[row][c4 * 4];
            p[0] = v.x; p[1] = v.y; p[2] = v.z; p[3] = v.w;
        }
        __syncthreads();
#pragma unroll 4
        for (int k = 0; k < 32; k++) {
            float aa[8], bb[8];
#pragma unroll
            for (int i = 0; i < 8; i++) aa[i] = sIn[rg + 16 * i][k];
#pragma unroll
            for (int i = 0; i < 8; i++) bb[i] = sW[cg + 16 * i][k];
#pragma unroll
            for (int i = 0; i < 8; i++)
#pragma unroll
                for (int j = 0; j < 8; j++) acc[i][j] = fmaf(aa[i], bb[j], acc[i][j]);
        }
        __syncthreads();
    }
#pragma unroll
    for (int i = 0; i < 8; i++) {
        int r = rbase + rg + 16 * i;
        if (r >= M) continue;
#pragma unroll
        for (int j = 0; j < 8; j++) {
            int c = cg + 16 * j;
            float v = acc[i][j] + bias[c];
            if (relu) v = fmaxf(v, 0.f);
            out[(size_t)r * 128 + c] = v;
        }
    }
}

// ---------------- relmsg[t,:] = (edge_lin[t,:] . wrw + wrb) * edge_lin[t,:] ----------------
__global__ void relmsg_kernel(const float* __restrict__ el, const float* __restrict__ wrw,
                              const float* __restrict__ wrb, float* __restrict__ rm)
{
    int t = blockIdx.x, tid = threadIdx.x;  // 128 threads
    __shared__ float warpred[4];
    __shared__ float wsh;
    float v = el[(size_t)t * HH + tid];
    float p = v * wrw[tid];
#pragma unroll
    for (int o = 16; o > 0; o >>= 1) p += __shfl_xor_sync(0xffffffffu, p, o);
    if ((tid & 31) == 0) warpred[tid >> 5] = p;
    __syncthreads();
    if (tid == 0) wsh = warpred[0] + warpred[1] + warpred[2] + warpred[3] + wrb[0];
    __syncthreads();
    rm[(size_t)t * HH + tid] = wsh * v;
}

// ---------------- x0 gather: x[i,:] = node_lin[node_ids[i],:] ----------------
__global__ void gather_kernel(const int* __restrict__ nids, const float* __restrict__ nl,
                              float* __restrict__ x, int n)
{
    int gt = blockIdx.x * blockDim.x + threadIdx.x;
    int i = gt >> 5;
    if (i >= n) return;
    int lane = gt & 31;
    *reinterpret_cast<float4*>(x + (size_t)i * HH + lane * 4) =
        *reinterpret_cast<const float4*>(nl + (size_t)__ldg(nids + i) * HH + lane * 4);
}

// ---------------- edge message + scatter: agg[dst] += relu(a*x[src] + relmsg[type]) ----------------
__global__ void msg_kernel(const int* __restrict__ ei, const int* __restrict__ eids,
                           const int* __restrict__ nids, const int* __restrict__ batch,
                           const float* __restrict__ attn, const float* __restrict__ x,
                           const float* __restrict__ relmsg, float* __restrict__ agg, int E)
{
    int gt = blockIdx.x * blockDim.x + threadIdx.x;
    int e = gt >> 5;
    if (e >= E) return;
    int lane = gt & 31;
    int src = __ldg(ei + e);
    int dst = __ldg(ei + E + e);
    int t = __ldg(eids + e);
    float a = __ldg(attn + (size_t)__ldg(batch + src) * VV + __ldg(nids + src));
    float4 xv = *reinterpret_cast<const float4*>(x + (size_t)src * HH + lane * 4);
    float4 rm = __ldg(reinterpret_cast<const float4*>(relmsg + (size_t)t * HH + lane * 4));
    float m0 = fmaxf(fmaf(a, xv.x, rm.x), 0.f);
    float m1 = fmaxf(fmaf(a, xv.y, rm.y), 0.f);
    float m2 = fmaxf(fmaf(a, xv.z, rm.z), 0.f);
    float m3 = fmaxf(fmaf(a, xv.w, rm.w), 0.f);
    float* p = agg + (size_t)dst * HH + lane * 4;
    asm volatile("red.global.add.v4.f32 [%0], {%1,%2,%3,%4};"
                 :: "l"(p), "f"(m0), "f"(m1), "f"(m2), "f"(m3) : "memory");
}

// ---------------- mean-pool accumulation ----------------
__global__ void pool_kernel(const int* __restrict__ batch, const float* __restrict__ x,
                            float* __restrict__ pooled, float* __restrict__ cnt, int n)
{
    int gt = blockIdx.x * blockDim.x + threadIdx.x;
    int i = gt >> 5;
    if (i >= n) return;
    int lane = gt & 31;
    int b = __ldg(batch + i);
    float4 v = *reinterpret_cast<const float4*>(x + (size_t)i * HH + lane * 4);
    float* p = pooled + (size_t)b * HH + lane * 4;
    asm volatile("red.global.add.v4.f32 [%0], {%1,%2,%3,%4};"
                 :: "l"(p), "f"(v.x), "f"(v.y), "f"(v.z), "f"(v.w) : "memory");
    if (lane == 0) atomicAdd(cnt + b, 1.0f);
}

// ---------------- per-graph head: mean pool, node branch, MLP ----------------
__global__ __launch_bounds__(128) void final_kernel(
    const float* __restrict__ ehr, const float* __restrict__ nemb,
    const float* __restrict__ lw, const float* __restrict__ lb,
    const float* __restrict__ pooled, const float* __restrict__ cnt,
    const float* __restrict__ mw, const float* __restrict__ mb,
    float* __restrict__ out)
{
    int b = blockIdx.x, tid = threadIdx.x;
    __shared__ float sE[128];
    __shared__ float cat[256];
    __shared__ float red4[4];
    __shared__ float sSum;
    const float* eb = ehr + (size_t)b * VV;

    float s = 0.f;
    for (int v = tid; v < VV; v += 128) s += eb[v];
#pragma unroll
    for (int o = 16; o > 0; o >>= 1) s += __shfl_xor_sync(0xffffffffu, s, o);
    if ((tid & 31) == 0) red4[tid >> 5] = s;
    __syncthreads();
    if (tid == 0) sSum = red4[0] + red4[1] + red4[2] + red4[3];
    __syncthreads();

    float accd = 0.f;
    for (int v0 = 0; v0 < VV; v0 += 128) {
        __syncthreads();
        sE[tid] = eb[v0 + tid];
        __syncthreads();
#pragma unroll 8
        for (int vv = 0; vv < 128; vv++)
            accd = fmaf(sE[vv], nemb[(size_t)(v0 + vv) * HH + tid], accd);
    }
    accd /= sSum;
    __syncthreads();
    sE[tid] = accd;
    __syncthreads();

    float xl = lb[tid];
#pragma unroll 8
    for (int d = 0; d < 128; d++) xl = fmaf(sE[d], lw[(size_t)tid * 128 + d], xl);
    cat[128 + tid] = xl;
    float c = fmaxf(cnt[b], 1.0f);
    cat[tid] = pooled[(size_t)b * HH + tid] / c;
    __syncthreads();
    if (tid < 25) {
        float o = mb[tid];
#pragma unroll 8
        for (int j = 0; j < 256; j++) o = fmaf(cat[j], mw[(size_t)tid * 256 + j], o);
        out[b * 25 + tid] = o;
    }
}

// ---------------- launch ----------------
extern "C" void kernel_launch(void* const* d_in, const int* in_sizes, int n_in,
                              void* d_out, int out_size)
{
    const int*   node_ids   = (const int*)d_in[0];
    const int*   edge_ids   = (const int*)d_in[1];
    const int*   edge_index = (const int*)d_in[2];
    const float* visit_node = (const float*)d_in[6];
    const float* ehr        = (const float*)d_in[7];
    const int*   batch      = (const int*)d_in[8];
    const float* node_emb   = (const float*)d_in[10];
    const float* edge_emb   = (const float*)d_in[11];
    const float* lin_w      = (const float*)d_in[12];
    const float* lin_b      = (const float*)d_in[13];
    const float* alpha_w    = (const float*)d_in[14];
    const float* beta_w     = (const float*)d_in[16];
    const float* beta_b     = (const float*)d_in[17];
    const float* conv_w     = (const float*)d_in[18];
    const float* conv_b     = (const float*)d_in[19];
    const float* wr_w       = (const float*)d_in[20];
    const float* wr_b       = (const float*)d_in[21];
    const float* epsp       = (const float*)d_in[22];
    const float* mlp_w      = (const float*)d_in[23];
    const float* mlp_b      = (const float*)d_in[24];

    const int N = in_sizes[0];
    const int E = in_sizes[1];
    const int B = in_sizes[7] / VV;
    const int NT = in_sizes[11] / HH;  // edge-type count (500)

    float *xA, *xB, *nl, *elin, *rm, *attn, *beta, *pooled, *cnt;
    cudaGetSymbolAddress((void**)&xA, g_xA);
    cudaGetSymbolAddress((void**)&xB, g_xB);
    cudaGetSymbolAddress((void**)&nl, g_node_lin);
    cudaGetSymbolAddress((void**)&elin, g_edge_lin);
    cudaGetSymbolAddress((void**)&rm, g_relmsg);
    cudaGetSymbolAddress((void**)&attn, g_attn);
    cudaGetSymbolAddress((void**)&beta, g_beta);
    cudaGetSymbolAddress((void**)&pooled, g_pooled);
    cudaGetSymbolAddress((void**)&cnt, g_cnt);

    // vocabulary-level precompute (4096 + 500 rows instead of 50000 + 800000)
    gemm128_kernel<<<(VV + 127) / 128, 256>>>(node_emb, nullptr, nullptr, 0, lin_w, lin_b, nl, VV, 0);
    gemm128_kernel<<<(NT + 127) / 128, 256>>>(edge_emb, nullptr, nullptr, 0, lin_w, lin_b, elin, NT, 0);
    gather_kernel<<<(N * 32 + 255) / 256, 256>>>(node_ids, nl, xA, N);

    for (int l = 0; l < 2; l++) {
        float* xcur = (l == 0) ? xA : xB;
        float* aggb = (l == 0) ? xB : xA;
        beta_kernel<<<(B * MVV * 32 + 255) / 256, 256>>>(visit_node, beta_w + (size_t)l * VV,
                                                         beta_b + l, beta, B * MVV);
        attn_kernel<<<dim3(VV / 256, B), 128>>>(visit_node, alpha_w + (size_t)l * VV * VV, beta, attn);
        relmsg_kernel<<<NT, 128>>>(elin, wr_w + (size_t)l * HH, wr_b + l, rm);
        cudaMemsetAsync(aggb, 0, (size_t)N * HH * sizeof(float));
        msg_kernel<<<(E * 32 + 255) / 256, 256>>>(edge_index, edge_ids, node_ids, batch,
                                                  attn, xcur, rm, aggb, E);
        // in-place: each block only reads/writes its own 128 rows, writes after all reads
        gemm128_kernel<<<(N + 127) / 128, 256>>>(aggb, xcur, epsp, l,
                                                 conv_w + (size_t)l * HH * HH, conv_b + (size_t)l * HH,
                                                 aggb, N, 1);
    }

    cudaMemsetAsync(pooled, 0, (size_t)BMAX * HH * sizeof(float));
    cudaMemsetAsync(cnt, 0, BMAX * sizeof(float));
    pool_kernel<<<(N * 32 + 255) / 256, 256>>>(batch, xA, pooled, cnt, N);
    final_kernel<<<B, 128>>>(ehr, node_emb, lin_w, lin_b, pooled, cnt, mlp_w, mlp_b, (float*)d_out);
}

// round 3
// speedup vs baseline: 2.2132x; 2.2132x over previous
#include <cuda_runtime.h>
#include <cstdint>

#define VV 4096
#define HH 128
#define MVV 20
#define NMAX 50000
#define ETYPES_MAX 512
#define BMAX 64

// ---------------- static scratch (no runtime allocation allowed) ----------------
__device__ __align__(16) float g_xA[(size_t)NMAX * HH];
__device__ __align__(16) float g_xB[(size_t)NMAX * HH];
__device__ __align__(16) float g_node_lin[VV * HH];
__device__ __align__(16) float g_edge_lin[ETYPES_MAX * HH];
__device__ __align__(16) float g_relmsg[ETYPES_MAX * HH];
__device__ __align__(16) float g_attn[BMAX * VV];
__device__ float g_beta[BMAX * MVV];
__device__ __align__(16) float g_pooled[BMAX * HH];
__device__ float g_cnt[BMAX];
__device__ __align__(16) float g_logits[(size_t)BMAX * MVV * VV];  // 21 MB

// ================= tf32 tensor-core GEMM: C[r,c] = sum_k A[r,k]*B[c,k] =================
// A: [M][4096] row-major (visit_node flattened), B: [4096][4096] row-major (alpha_w layer)
// block tile 128x128, k-step 32, 8 warps (2x4), warp tile 64x32, mma m16n8k8.
// smem layout [k][m] (+4 pad) -> fragment LDS are conflict-free (addr%32 = 4*tig+gid).
__global__ __launch_bounds__(256) void tf32_gemm_kernel(
    const float* __restrict__ A, const float* __restrict__ Bm, float* __restrict__ C)
{
    __shared__ float sA[32][132];
    __shared__ float sB[32][132];

    const int tid = threadIdx.x;
    const int warpId = tid >> 5, lane = tid & 31;
    const int wr = warpId >> 2, wc = warpId & 3;
    const int gid = lane >> 2, tig = lane & 3;
    const int rbase = blockIdx.y * 128;
    const int cbase = blockIdx.x * 128;

    const int mrow = tid >> 3;        // 0..31 (then +32*i)
    const int kq = (tid & 7) * 4;     // k offset within 32

    float4 ra[4], rb[4];
    float acc[4][4][4];
#pragma unroll
    for (int i = 0; i < 4; i++)
#pragma unroll
        for (int j = 0; j < 4; j++)
#pragma unroll
            for (int q = 0; q < 4; q++) acc[i][j][q] = 0.f;

#pragma unroll
    for (int i = 0; i < 4; i++) {
        ra[i] = *reinterpret_cast<const float4*>(A + (size_t)(rbase + mrow + 32 * i) * VV + kq);
        rb[i] = *reinterpret_cast<const float4*>(Bm + (size_t)(cbase + mrow + 32 * i) * VV + kq);
    }

    for (int kt = 0; kt < VV / 32; kt++) {
        // store staged regs to smem (tf32-convert once here)
#pragma unroll
        for (int i = 0; i < 4; i++) {
            int m = mrow + 32 * i;
            float v[4] = {ra[i].x, ra[i].y, ra[i].z, ra[i].w};
            float w[4] = {rb[i].x, rb[i].y, rb[i].z, rb[i].w};
#pragma unroll
            for (int j = 0; j < 4; j++) {
                uint32_t ta, tb;
                asm("cvt.rna.tf32.f32 %0, %1;" : "=r"(ta) : "f"(v[j]));
                asm("cvt.rna.tf32.f32 %0, %1;" : "=r"(tb) : "f"(w[j]));
                sA[kq + j][m] = __uint_as_float(ta);
                sB[kq + j][m] = __uint_as_float(tb);
            }
        }
        __syncthreads();

        if (kt + 1 < VV / 32) {
            const float* Ap = A + (size_t)(kt + 1) * 32 + kq;
            const float* Bp = Bm + (size_t)(kt + 1) * 32 + kq;
#pragma unroll
            for (int i = 0; i < 4; i++) {
                ra[i] = *reinterpret_cast<const float4*>(Ap + (size_t)(rbase + mrow + 32 * i) * VV);
                rb[i] = *reinterpret_cast<const float4*>(Bp + (size_t)(cbase + mrow + 32 * i) * VV);
            }
        }

#pragma unroll
        for (int ks = 0; ks < 4; ks++) {
            const int k0 = ks * 8;
            uint32_t af[4][4], bf[4][2];
#pragma unroll
            for (int mf = 0; mf < 4; mf++) {
                int r0 = wr * 64 + mf * 16 + gid;
                af[mf][0] = __float_as_uint(sA[k0 + tig][r0]);
                af[mf][1] = __float_as_uint(sA[k0 + tig][r0 + 8]);
                af[mf][2] = __float_as_uint(sA[k0 + tig + 4][r0]);
                af[mf][3] = __float_as_uint(sA[k0 + tig + 4][r0 + 8]);
            }
#pragma unroll
            for (int nf = 0; nf < 4; nf++) {
                int c0 = wc * 32 + nf * 8 + gid;
                bf[nf][0] = __float_as_uint(sB[k0 + tig][c0]);
                bf[nf][1] = __float_as_uint(sB[k0 + tig + 4][c0]);
            }
#pragma unroll
            for (int mf = 0; mf < 4; mf++)
#pragma unroll
                for (int nf = 0; nf < 4; nf++) {
                    asm volatile(
                        "mma.sync.aligned.m16n8k8.row.col.f32.tf32.tf32.f32 "
                        "{%0,%1,%2,%3}, {%4,%5,%6,%7}, {%8,%9}, {%0,%1,%2,%3};"
                        : "+f"(acc[mf][nf][0]), "+f"(acc[mf][nf][1]),
                          "+f"(acc[mf][nf][2]), "+f"(acc[mf][nf][3])
                        : "r"(af[mf][0]), "r"(af[mf][1]), "r"(af[mf][2]), "r"(af[mf][3]),
                          "r"(bf[nf][0]), "r"(bf[nf][1]));
                }
        }
        __syncthreads();
    }

#pragma unroll
    for (int mf = 0; mf < 4; mf++) {
        int r0 = rbase + wr * 64 + mf * 16 + gid;
#pragma unroll
        for (int nf = 0; nf < 4; nf++) {
            int c0 = cbase + wc * 32 + nf * 8 + tig * 2;
            *reinterpret_cast<float2*>(C + (size_t)r0 * VV + c0) =
                make_float2(acc[mf][nf][0], acc[mf][nf][1]);
            *reinterpret_cast<float2*>(C + (size_t)(r0 + 8) * VV + c0) =
                make_float2(acc[mf][nf][2], acc[mf][nf][3]);
        }
    }
}

// ---------------- softmax over MV + beta reduce: attn[b,v] ----------------
__global__ __launch_bounds__(256) void softmax_beta_kernel(
    const float* __restrict__ logits, const float* __restrict__ beta,
    float* __restrict__ attn)
{
    __shared__ float sBeta[MVV];
    const int b = blockIdx.y;
    const int v = blockIdx.x * 256 + threadIdx.x;
    if (threadIdx.x < MVV) sBeta[threadIdx.x] = beta[b * MVV + threadIdx.x];
    __syncthreads();
    const float* lp = logits + (size_t)b * MVV * VV + v;
    float z[MVV];
    float mx = -1e30f;
#pragma unroll
    for (int m = 0; m < MVV; m++) {
        z[m] = lp[(size_t)m * VV];
        mx = fmaxf(mx, z[m]);
    }
    float se = 0.f, sw = 0.f;
#pragma unroll
    for (int m = 0; m < MVV; m++) {
        float e = __expf(z[m] - mx);
        se += e;
        sw += e * sBeta[m];
    }
    attn[(size_t)b * VV + v] = sw / se;
}

// ---------------- beta[b,mv] = tanh(vn[b,mv,:] . bw + bb) * exp(0.01*(MV-mv)) ----------------
__global__ void beta_kernel(const float* __restrict__ vn, const float* __restrict__ bw,
                            const float* __restrict__ bb, float* __restrict__ beta, int BMV)
{
    int gw = (blockIdx.x * blockDim.x + threadIdx.x) >> 5;
    int lane = threadIdx.x & 31;
    if (gw >= BMV) return;
    int mv = gw % MVV;
    const float* row = vn + (size_t)gw * VV;
    float s = 0.f;
    for (int k = lane; k < VV; k += 32) s = fmaf(row[k], bw[k], s);
#pragma unroll
    for (int o = 16; o > 0; o >>= 1) s += __shfl_xor_sync(0xffffffffu, s, o);
    if (lane == 0) beta[gw] = tanhf(s + bb[0]) * __expf(0.01f * (float)(MVV - mv));
}

// ---------------- generic out[r,c] = act( (a1[r,:] + s*a2[r,:]) @ w[c,:] + bias[c] ), K=N=128 ----------------
__global__ __launch_bounds__(256) void gemm128_kernel(
    const float* __restrict__ a1, const float* __restrict__ a2,
    const float* __restrict__ epsp, int layer,
    const float* __restrict__ w, const float* __restrict__ bias,
    float* __restrict__ out, int M, int relu)
{
    __shared__ float sIn[128][33];
    __shared__ float sW[128][33];
    const int tid = threadIdx.x;
    const int rg = tid >> 4, cg = tid & 15;
    const int rbase = blockIdx.x * 128;
    float scale = 0.f;
    if (a2) scale = 1.0f + epsp[layer];

    float acc[8][8];
#pragma unroll
    for (int i = 0; i < 8; i++)
#pragma unroll
        for (int j = 0; j < 8; j++) acc[i][j] = 0.f;

    for (int k0 = 0; k0 < 128; k0 += 32) {
#pragma unroll
        for (int f = tid; f < 1024; f += 256) {
            int row = f >> 3, c4 = f & 7;
            int r = rbase + row;
            float4 v = make_float4(0.f, 0.f, 0.f, 0.f);
            if (r < M) {
                v = *reinterpret_cast<const float4*>(a1 + (size_t)r * 128 + k0 + c4 * 4);
                if (a2) {
                    float4 u = *reinterpret_cast<const float4*>(a2 + (size_t)r * 128 + k0 + c4 * 4);
                    v.x = fmaf(scale, u.x, v.x); v.y = fmaf(scale, u.y, v.y);
                    v.z = fmaf(scale, u.z, v.z); v.w = fmaf(scale, u.w, v.w);
                }
            }
            float* p = &sIn[row][c4 * 4];
            p[0] = v.x; p[1] = v.y; p[2] = v.z; p[3] = v.w;
        }
#pragma unroll
        for (int f = tid; f < 1024; f += 256) {
            int row = f >> 3, c4 = f & 7;
            float4 v = *reinterpret_cast<const float4*>(w + (size_t)row * 128 + k0 + c4 * 4);
            float* p = &sW[row][c4 * 4];
            p[0] = v.x; p[1] = v.y; p[2] = v.z; p[3] = v.w;
        }
        __syncthreads();
#pragma unroll 4
        for (int k = 0; k < 32; k++) {
            float aa[8], bb[8];
#pragma unroll
            for (int i = 0; i < 8; i++) aa[i] = sIn[rg + 16 * i][k];
#pragma unroll
            for (int i = 0; i < 8; i++) bb[i] = sW[cg + 16 * i][k];
#pragma unroll
            for (int i = 0; i < 8; i++)
#pragma unroll
                for (int j = 0; j < 8; j++) acc[i][j] = fmaf(aa[i], bb[j], acc[i][j]);
        }
        __syncthreads();
    }
#pragma unroll
    for (int i = 0; i < 8; i++) {
        int r = rbase + rg + 16 * i;
        if (r >= M) continue;
#pragma unroll
        for (int j = 0; j < 8; j++) {
            int c = cg + 16 * j;
            float v = acc[i][j] + bias[c];
            if (relu) v = fmaxf(v, 0.f);
            out[(size_t)r * 128 + c] = v;
        }
    }
}

// ---------------- relmsg[t,:] = (edge_lin[t,:] . wrw + wrb) * edge_lin[t,:] ----------------
__global__ void relmsg_kernel(const float* __restrict__ el, const float* __restrict__ wrw,
                              const float* __restrict__ wrb, float* __restrict__ rm)
{
    int t = blockIdx.x, tid = threadIdx.x;  // 128 threads
    __shared__ float warpred[4];
    __shared__ float wsh;
    float v = el[(size_t)t * HH + tid];
    float p = v * wrw[tid];
#pragma unroll
    for (int o = 16; o > 0; o >>= 1) p += __shfl_xor_sync(0xffffffffu, p, o);
    if ((tid & 31) == 0) warpred[tid >> 5] = p;
    __syncthreads();
    if (tid == 0) wsh = warpred[0] + warpred[1] + warpred[2] + warpred[3] + wrb[0];
    __syncthreads();
    rm[(size_t)t * HH + tid] = wsh * v;
}

// ---------------- x0 gather: x[i,:] = node_lin[node_ids[i],:] ----------------
__global__ void gather_kernel(const int* __restrict__ nids, const float* __restrict__ nl,
                              float* __restrict__ x, int n)
{
    int gt = blockIdx.x * blockDim.x + threadIdx.x;
    int i = gt >> 5;
    if (i >= n) return;
    int lane = gt & 31;
    *reinterpret_cast<float4*>(x + (size_t)i * HH + lane * 4) =
        *reinterpret_cast<const float4*>(nl + (size_t)__ldg(nids + i) * HH + lane * 4);
}

// ---------------- edge message + scatter: agg[dst] += relu(a*x[src] + relmsg[type]) ----------------
__global__ void msg_kernel(const int* __restrict__ ei, const int* __restrict__ eids,
                           const int* __restrict__ nids, const int* __restrict__ batch,
                           const float* __restrict__ attn, const float* __restrict__ x,
                           const float* __restrict__ relmsg, float* __restrict__ agg, int E)
{
    int gt = blockIdx.x * blockDim.x + threadIdx.x;
    int e = gt >> 5;
    if (e >= E) return;
    int lane = gt & 31;
    int src = __ldg(ei + e);
    int dst = __ldg(ei + E + e);
    int t = __ldg(eids + e);
    float a = __ldg(attn + (size_t)__ldg(batch + src) * VV + __ldg(nids + src));
    float4 xv = *reinterpret_cast<const float4*>(x + (size_t)src * HH + lane * 4);
    float4 rm = __ldg(reinterpret_cast<const float4*>(relmsg + (size_t)t * HH + lane * 4));
    float m0 = fmaxf(fmaf(a, xv.x, rm.x), 0.f);
    float m1 = fmaxf(fmaf(a, xv.y, rm.y), 0.f);
    float m2 = fmaxf(fmaf(a, xv.z, rm.z), 0.f);
    float m3 = fmaxf(fmaf(a, xv.w, rm.w), 0.f);
    float* p = agg + (size_t)dst * HH + lane * 4;
    asm volatile("red.global.add.v4.f32 [%0], {%1,%2,%3,%4};"
                 :: "l"(p), "f"(m0), "f"(m1), "f"(m2), "f"(m3) : "memory");
}

// ---------------- mean-pool accumulation ----------------
__global__ void pool_kernel(const int* __restrict__ batch, const float* __restrict__ x,
                            float* __restrict__ pooled, float* __restrict__ cnt, int n)
{
    int gt = blockIdx.x * blockDim.x + threadIdx.x;
    int i = gt >> 5;
    if (i >= n) return;
    int lane = gt & 31;
    int b = __ldg(batch + i);
    float4 v = *reinterpret_cast<const float4*>(x + (size_t)i * HH + lane * 4);
    float* p = pooled + (size_t)b * HH + lane * 4;
    asm volatile("red.global.add.v4.f32 [%0], {%1,%2,%3,%4};"
                 :: "l"(p), "f"(v.x), "f"(v.y), "f"(v.z), "f"(v.w) : "memory");
    if (lane == 0) atomicAdd(cnt + b, 1.0f);
}

// ---------------- per-graph head: mean pool, node branch, MLP ----------------
__global__ __launch_bounds__(128) void final_kernel(
    const float* __restrict__ ehr, const float* __restrict__ nemb,
    const float* __restrict__ lw, const float* __restrict__ lb,
    const float* __restrict__ pooled, const float* __restrict__ cnt,
    const float* __restrict__ mw, const float* __restrict__ mb,
    float* __restrict__ out)
{
    int b = blockIdx.x, tid = threadIdx.x;
    __shared__ float sE[128];
    __shared__ float cat[256];
    __shared__ float red4[4];
    __shared__ float sSum;
    const float* eb = ehr + (size_t)b * VV;

    float s = 0.f;
    for (int v = tid; v < VV; v += 128) s += eb[v];
#pragma unroll
    for (int o = 16; o > 0; o >>= 1) s += __shfl_xor_sync(0xffffffffu, s, o);
    if ((tid & 31) == 0) red4[tid >> 5] = s;
    __syncthreads();
    if (tid == 0) sSum = red4[0] + red4[1] + red4[2] + red4[3];
    __syncthreads();

    float accd = 0.f;
    for (int v0 = 0; v0 < VV; v0 += 128) {
        __syncthreads();
        sE[tid] = eb[v0 + tid];
        __syncthreads();
#pragma unroll 8
        for (int vv = 0; vv < 128; vv++)
            accd = fmaf(sE[vv], nemb[(size_t)(v0 + vv) * HH + tid], accd);
    }
    accd /= sSum;
    __syncthreads();
    sE[tid] = accd;
    __syncthreads();

    float xl = lb[tid];
#pragma unroll 8
    for (int d = 0; d < 128; d++) xl = fmaf(sE[d], lw[(size_t)tid * 128 + d], xl);
    cat[128 + tid] = xl;
    float c = fmaxf(cnt[b], 1.0f);
    cat[tid] = pooled[(size_t)b * HH + tid] / c;
    __syncthreads();
    if (tid < 25) {
        float o = mb[tid];
#pragma unroll 8
        for (int j = 0; j < 256; j++) o = fmaf(cat[j], mw[(size_t)tid * 256 + j], o);
        out[b * 25 + tid] = o;
    }
}

// ---------------- launch ----------------
extern "C" void kernel_launch(void* const* d_in, const int* in_sizes, int n_in,
                              void* d_out, int out_size)
{
    const int*   node_ids   = (const int*)d_in[0];
    const int*   edge_ids   = (const int*)d_in[1];
    const int*   edge_index = (const int*)d_in[2];
    const float* visit_node = (const float*)d_in[6];
    const float* ehr        = (const float*)d_in[7];
    const int*   batch      = (const int*)d_in[8];
    const float* node_emb   = (const float*)d_in[10];
    const float* edge_emb   = (const float*)d_in[11];
    const float* lin_w      = (const float*)d_in[12];
    const float* lin_b      = (const float*)d_in[13];
    const float* alpha_w    = (const float*)d_in[14];
    const float* beta_w     = (const float*)d_in[16];
    const float* beta_b     = (const float*)d_in[17];
    const float* conv_w     = (const float*)d_in[18];
    const float* conv_b     = (const float*)d_in[19];
    const float* wr_w       = (const float*)d_in[20];
    const float* wr_b       = (const float*)d_in[21];
    const float* epsp       = (const float*)d_in[22];
    const float* mlp_w      = (const float*)d_in[23];
    const float* mlp_b      = (const float*)d_in[24];

    const int N = in_sizes[0];
    const int E = in_sizes[1];
    const int B = in_sizes[7] / VV;
    const int NT = in_sizes[11] / HH;  // edge-type count (500)

    float *xA, *xB, *nl, *elin, *rm, *attn, *beta, *pooled, *cnt, *logits;
    cudaGetSymbolAddress((void**)&xA, g_xA);
    cudaGetSymbolAddress((void**)&xB, g_xB);
    cudaGetSymbolAddress((void**)&nl, g_node_lin);
    cudaGetSymbolAddress((void**)&elin, g_edge_lin);
    cudaGetSymbolAddress((void**)&rm, g_relmsg);
    cudaGetSymbolAddress((void**)&attn, g_attn);
    cudaGetSymbolAddress((void**)&beta, g_beta);
    cudaGetSymbolAddress((void**)&pooled, g_pooled);
    cudaGetSymbolAddress((void**)&cnt, g_cnt);
    cudaGetSymbolAddress((void**)&logits, g_logits);

    // vocabulary-level precompute (4096 + 500 rows instead of 50000 + 800000)
    gemm128_kernel<<<(VV + 127) / 128, 256>>>(node_emb, nullptr, nullptr, 0, lin_w, lin_b, nl, VV, 0);
    gemm128_kernel<<<(NT + 127) / 128, 256>>>(edge_emb, nullptr, nullptr, 0, lin_w, lin_b, elin, NT, 0);
    gather_kernel<<<(N * 32 + 255) / 256, 256>>>(node_ids, nl, xA, N);

    const int Mrows = B * MVV;  // 1280
    for (int l = 0; l < 2; l++) {
        float* xcur = (l == 0) ? xA : xB;
        float* aggb = (l == 0) ? xB : xA;
        beta_kernel<<<(B * MVV * 32 + 255) / 256, 256>>>(visit_node, beta_w + (size_t)l * VV,
                                                         beta_b + l, beta, B * MVV);
        tf32_gemm_kernel<<<dim3(VV / 128, Mrows / 128), 256>>>(
            visit_node, alpha_w + (size_t)l * VV * VV, logits);
        softmax_beta_kernel<<<dim3(VV / 256, B), 256>>>(logits, beta, attn);
        relmsg_kernel<<<NT, 128>>>(elin, wr_w + (size_t)l * HH, wr_b + l, rm);
        cudaMemsetAsync(aggb, 0, (size_t)N * HH * sizeof(float));
        msg_kernel<<<(E * 32 + 255) / 256, 256>>>(edge_index, edge_ids, node_ids, batch,
                                                  attn, xcur, rm, aggb, E);
        // in-place: each block only reads/writes its own 128 rows, writes after all reads
        gemm128_kernel<<<(N + 127) / 128, 256>>>(aggb, xcur, epsp, l,
                                                 conv_w + (size_t)l * HH * HH, conv_b + (size_t)l * HH,
                                                 aggb, N, 1);
    }

    cudaMemsetAsync(pooled, 0, (size_t)BMAX * HH * sizeof(float));
    cudaMemsetAsync(cnt, 0, BMAX * sizeof(float));
    pool_kernel<<<(N * 32 + 255) / 256, 256>>>(batch, xA, pooled, cnt, N);
    final_kernel<<<B, 128>>>(ehr, node_emb, lin_w, lin_b, pooled, cnt, mlp_w, mlp_b, (float*)d_out);
}